// round 7
// baseline (speedup 1.0000x reference)
#include <cuda_runtime.h>
#include <cstddef>

// DynamicFilterLayer: out[n,c,h,w] = sum_{i,j} xpad[n,c,h+i,w+j] * filters[n,i*9+j,h,w] + bias[n,0,h,w]
// N=2, C=8, H=256, W=512, K=9, pad=4.
// R5: split the 8 channels into 2 groups of 4 -> grid 1024 (2x warps, ~2x occupancy).
// Sibling blocks (same (n,h), different channel group) are adjacent in bid so they
// run in the same wave; the duplicated tap reads hit L2 (166KB/row << 126MB).

#define N_  2
#define C_  8
#define CG  4    // channels per block
#define H_  256
#define W_  512
#define KK  9
#define PAD 4
#define WPT 4    // output columns per thread

__global__ void __launch_bounds__(128) dfl_kernel(
    const float* __restrict__ x,      // [N, C, H, W]
    const float* __restrict__ f,      // [N, 81, H, W]
    const float* __restrict__ b,      // [N, 1, H, W]
    float* __restrict__ out)          // [N, C, H, W]
{
    const int row = blockIdx.x >> 1;         // (n, h) row id
    const int c0  = (blockIdx.x & 1) * CG;   // channel group base: 0 or 4
    const int n   = row >> 8;                // row / H_
    const int h   = row & 255;               // row % H_
    const int w0  = threadIdx.x * WPT;       // 128 threads * 4 = 512 = W_

    const size_t HW = (size_t)H_ * W_;

    // accumulators initialized with bias
    float acc[CG][WPT];
    {
        const float4 bv = *reinterpret_cast<const float4*>(b + (size_t)n * HW + (size_t)h * W_ + w0);
        #pragma unroll
        for (int c = 0; c < CG; c++) {
            acc[c][0] = bv.x; acc[c][1] = bv.y; acc[c][2] = bv.z; acc[c][3] = bv.w;
        }
    }

    const float* fbase = f + ((size_t)n * (KK * KK)) * HW + (size_t)h * W_ + w0; // tap t stride = HW
    const float* xbase = x + ((size_t)n * C_ + c0) * HW;                         // this block's 4 channels

    const bool interior = (w0 >= PAD) && (w0 + WPT - 1 + PAD < W_);  // [w0-4, w0+7] in-range

    const int i0 = (h < PAD) ? (PAD - h) : 0;
    const int i1 = (h > H_ - 1 - PAD) ? (PAD + H_ - h) : KK;

    for (int i = i0; i < i1; i++) {
        const int hi = h + i - PAD;

        // preload the 9 tap vectors for this i (shared across the 4 channels)
        float tap[KK][WPT];
        #pragma unroll
        for (int j = 0; j < KK; j++) {
            const float4 t4 = *reinterpret_cast<const float4*>(fbase + (size_t)(i * KK + j) * HW);
            tap[j][0] = t4.x; tap[j][1] = t4.y; tap[j][2] = t4.z; tap[j][3] = t4.w;
        }

        #pragma unroll
        for (int c = 0; c < CG; c++) {
            const float* xr = xbase + (size_t)c * HW + (size_t)hi * W_ + w0;

            // sliding window of x: covers w0-4 .. w0+7 (12 values)
            float xw[WPT + KK - 1];
            if (interior) {
                const float4 a0 = *reinterpret_cast<const float4*>(xr - 4);
                const float4 a1 = *reinterpret_cast<const float4*>(xr);
                const float4 a2 = *reinterpret_cast<const float4*>(xr + 4);
                xw[0] = a0.x; xw[1]  = a0.y; xw[2]  = a0.z; xw[3]  = a0.w;
                xw[4] = a1.x; xw[5]  = a1.y; xw[6]  = a1.z; xw[7]  = a1.w;
                xw[8] = a2.x; xw[9]  = a2.y; xw[10] = a2.z; xw[11] = a2.w;
            } else {
                #pragma unroll
                for (int k = 0; k < WPT + KK - 1; k++) {
                    const int wi = w0 - PAD + k;
                    xw[k] = (wi >= 0 && wi < W_) ? xr[k - PAD] : 0.0f;
                }
            }

            #pragma unroll
            for (int j = 0; j < KK; j++) {
                #pragma unroll
                for (int w = 0; w < WPT; w++) {
                    acc[c][w] = fmaf(xw[j + w], tap[j][w], acc[c][w]);
                }
            }
        }
    }

    // store results
    float* obase = out + ((size_t)n * C_ + c0) * HW + (size_t)h * W_ + w0;
    #pragma unroll
    for (int c = 0; c < CG; c++) {
        float4 r;
        r.x = acc[c][0]; r.y = acc[c][1]; r.z = acc[c][2]; r.w = acc[c][3];
        *reinterpret_cast<float4*>(obase + (size_t)c * HW) = r;
    }
}

extern "C" void kernel_launch(void* const* d_in, const int* in_sizes, int n_in,
                              void* d_out, int out_size)
{
    const float* x = (const float*)d_in[0];   // x_in       [2, 8, 256, 512]
    const float* f = (const float*)d_in[1];   // filters    [2, 81, 256, 512]
    const float* b = (const float*)d_in[2];   // biases     [2, 1, 256, 512]
    float* out = (float*)d_out;

    dim3 grid(N_ * H_ * 2);  // 1024 blocks: (n,h) x 2 channel groups
    dim3 block(128);         // 128 threads * WPT(4) = 512 = W
    dfl_kernel<<<grid, block>>>(x, f, b, out);
}

// round 8
// speedup vs baseline: 1.5264x; 1.5264x over previous
#include <cuda_runtime.h>
#include <cstddef>

// DynamicFilterLayer: out[n,c,h,w] = sum_{i,j} xpad[n,c,h+i,w+j] * filters[n,i*9+j,h,w] + bias[n,0,h,w]
// N=2, C=8, H=256, W=512, K=9, pad=4.
// R7: grid 512 (tap stream read once); per-i front-batched loads (9 taps + 12 x) for
// high MLP; strength-reduced addressing (immediate LDG offsets); predicated edge loads.

#define N_  2
#define C_  8
#define H_  256
#define W_  512
#define KK  9
#define PAD 4
#define WPT 4   // output columns per thread

__global__ void __launch_bounds__(128) dfl_kernel(
    const float* __restrict__ x,      // [N, C, H, W]
    const float* __restrict__ f,      // [N, 81, H, W]
    const float* __restrict__ b,      // [N, 1, H, W]
    float* __restrict__ out)          // [N, C, H, W]
{
    const int n  = blockIdx.x >> 8;      // / H_
    const int h  = blockIdx.x & 255;     // % H_
    const int w0 = threadIdx.x * WPT;    // 128 threads * 4 = 512 = W_

    const size_t HW = (size_t)H_ * W_;

    // accumulators initialized with bias
    float acc[C_][WPT];
    {
        const float4 bv = *reinterpret_cast<const float4*>(b + (size_t)n * HW + (size_t)h * W_ + w0);
        #pragma unroll
        for (int c = 0; c < C_; c++) {
            acc[c][0] = bv.x; acc[c][1] = bv.y; acc[c][2] = bv.z; acc[c][3] = bv.w;
        }
    }

    const int i0 = (h < PAD) ? (PAD - h) : 0;
    const int i1 = (h > H_ - 1 - PAD) ? (PAD + H_ - h) : KK;

    // Two walking pointers; all per-j / per-c offsets are compile-time constants that
    // fold into the LDG immediate (j*HW*4B <= 4.2MB, c*HW*4B <= 3.7MB, both < +-8MB).
    const float* ftap = f + (size_t)n * (KK * KK) * HW + (size_t)h * W_ + w0 + (size_t)i0 * KK * HW;
    const float* xrow = x + (size_t)n * C_ * HW + (size_t)(h + i0 - PAD) * W_ + w0;

    const bool has_lo = (w0 >= PAD);             // false only for lane with w0==0
    const bool has_hi = (w0 + WPT + PAD <= W_);  // false only for lane with w0==508

    for (int i = i0; i < i1; i++) {
        // ---- batch 1: all 9 tap vectors (MLP 9) ----
        float4 t[KK];
        #pragma unroll
        for (int j = 0; j < KK; j++)
            t[j] = *reinterpret_cast<const float4*>(ftap + (size_t)j * HW);

        // ---- batch 2: x windows for channels 0..3 (12 more loads in flight) ----
        float4 lo[4], md[4], hi[4];
        #pragma unroll
        for (int c = 0; c < 4; c++) {
            const float* xr = xrow + (size_t)c * HW;
            float4 vl = make_float4(0.f, 0.f, 0.f, 0.f);
            float4 vh = make_float4(0.f, 0.f, 0.f, 0.f);
            if (has_lo) vl = *reinterpret_cast<const float4*>(xr - 4);
            md[c] = *reinterpret_cast<const float4*>(xr);
            if (has_hi) vh = *reinterpret_cast<const float4*>(xr + 4);
            lo[c] = vl; hi[c] = vh;
        }

        // ---- compute channels 0..3 ----
        #pragma unroll
        for (int c = 0; c < 4; c++) {
            const float xw[WPT + KK - 1] = {
                lo[c].x, lo[c].y, lo[c].z, lo[c].w,
                md[c].x, md[c].y, md[c].z, md[c].w,
                hi[c].x, hi[c].y, hi[c].z, hi[c].w };
            #pragma unroll
            for (int j = 0; j < KK; j++) {
                const float tj0 = t[j].x, tj1 = t[j].y, tj2 = t[j].z, tj3 = t[j].w;
                acc[c][0] = fmaf(xw[j + 0], tj0, acc[c][0]);
                acc[c][1] = fmaf(xw[j + 1], tj1, acc[c][1]);
                acc[c][2] = fmaf(xw[j + 2], tj2, acc[c][2]);
                acc[c][3] = fmaf(xw[j + 3], tj3, acc[c][3]);
            }
        }

        // ---- batch 3: x windows for channels 4..7 ----
        #pragma unroll
        for (int c = 0; c < 4; c++) {
            const float* xr = xrow + (size_t)(c + 4) * HW;
            float4 vl = make_float4(0.f, 0.f, 0.f, 0.f);
            float4 vh = make_float4(0.f, 0.f, 0.f, 0.f);
            if (has_lo) vl = *reinterpret_cast<const float4*>(xr - 4);
            md[c] = *reinterpret_cast<const float4*>(xr);
            if (has_hi) vh = *reinterpret_cast<const float4*>(xr + 4);
            lo[c] = vl; hi[c] = vh;
        }

        // ---- compute channels 4..7 ----
        #pragma unroll
        for (int c = 0; c < 4; c++) {
            const float xw[WPT + KK - 1] = {
                lo[c].x, lo[c].y, lo[c].z, lo[c].w,
                md[c].x, md[c].y, md[c].z, md[c].w,
                hi[c].x, hi[c].y, hi[c].z, hi[c].w };
            #pragma unroll
            for (int j = 0; j < KK; j++) {
                const float tj0 = t[j].x, tj1 = t[j].y, tj2 = t[j].z, tj3 = t[j].w;
                acc[c + 4][0] = fmaf(xw[j + 0], tj0, acc[c + 4][0]);
                acc[c + 4][1] = fmaf(xw[j + 1], tj1, acc[c + 4][1]);
                acc[c + 4][2] = fmaf(xw[j + 2], tj2, acc[c + 4][2]);
                acc[c + 4][3] = fmaf(xw[j + 3], tj3, acc[c + 4][3]);
            }
        }

        ftap += (size_t)KK * HW;   // next filter row block
        xrow += W_;                // next input row
    }

    // store results
    float* obase = out + (size_t)n * C_ * HW + (size_t)h * W_ + w0;
    #pragma unroll
    for (int c = 0; c < C_; c++) {
        float4 r;
        r.x = acc[c][0]; r.y = acc[c][1]; r.z = acc[c][2]; r.w = acc[c][3];
        *reinterpret_cast<float4*>(obase + (size_t)c * HW) = r;
    }
}

extern "C" void kernel_launch(void* const* d_in, const int* in_sizes, int n_in,
                              void* d_out, int out_size)
{
    const float* x = (const float*)d_in[0];   // x_in       [2, 8, 256, 512]
    const float* f = (const float*)d_in[1];   // filters    [2, 81, 256, 512]
    const float* b = (const float*)d_in[2];   // biases     [2, 1, 256, 512]
    float* out = (float*)d_out;

    dim3 grid(N_ * H_);   // 512 blocks, one per (n, h) row
    dim3 block(128);      // 128 threads * WPT(4) = 512 = W
    dfl_kernel<<<grid, block>>>(x, f, b, out);
}